// round 1
// baseline (speedup 1.0000x reference)
#include <cuda_runtime.h>
#include <cuda_bf16.h>

// Problem shape (LogRegBaseline): B=64, T=2048, V=512
#define BB     64
#define TT     2048
#define VV     512
#define TM1    (TT - 1)          // 2047 output positions
#define CHUNK  128               // time positions per emit CTA
#define NCHUNK ((TM1 + CHUNK - 1) / CHUNK)   // 16

// Scratch (device globals; no allocation allowed)
__device__ int   g_ft[BB * VV];                 // first-activation time per (b, v); TT if never
__device__ float g_Wt[VV * VV];                 // W transposed: Wt[v*VV + u] = W[u*VV + v]
__device__ float g_states[BB * NCHUNK * VV];    // prefix logits at each chunk boundary

// ---------------------------------------------------------------------------
// Kernel 1: first activation time per (b, v). Grid: BB blocks x VV threads.
// Coalesced scan over t (512 consecutive v per row), collective early exit
// once all 512 codes in this batch row have activated. Unroll 8 for MLP.
// ---------------------------------------------------------------------------
__global__ void find_first(const float* __restrict__ codes) {
    const int b = blockIdx.x;
    const int v = threadIdx.x;
    __shared__ int s_rem;
    if (v == 0) s_rem = VV;
    __syncthreads();

    const float* p = codes + (size_t)b * TT * VV + v;
    int  myft  = TT;
    bool found = false;

    for (int t0 = 0; t0 < TT; t0 += 8) {
        if (!found) {
            float x[8];
#pragma unroll
            for (int k = 0; k < 8; k++) x[k] = p[(size_t)(t0 + k) * VV];
#pragma unroll
            for (int k = 0; k < 8; k++) {
                if (!found && x[k] != 0.0f) { found = true; myft = t0 + k; }
            }
            if (found) atomicAdd(&s_rem, -1);
        }
        __syncthreads();
        int rem = s_rem;     // all iteration-t0 decrements landed before the barrier
        __syncthreads();     // no thread starts next iteration's adds before all read
        if (rem == 0) break;
    }
    g_ft[b * VV + v] = myft;
}

// ---------------------------------------------------------------------------
// Kernel 2: transpose W (row-major [V,V], W[u,v]) into Wt[v,u].
// Grid: (VV/32, VV/32), block (32, 8). Classic smem tile, +1 pad.
// ---------------------------------------------------------------------------
__global__ void transpose_w(const float* __restrict__ W) {
    __shared__ float tile[32][33];
    int x = blockIdx.x * 32 + threadIdx.x;   // v
    int y = blockIdx.y * 32 + threadIdx.y;   // u base
#pragma unroll
    for (int j = 0; j < 32; j += 8)
        tile[threadIdx.y + j][threadIdx.x] = W[(size_t)(y + j) * VV + x];
    __syncthreads();
    x = blockIdx.y * 32 + threadIdx.x;       // u
    y = blockIdx.x * 32 + threadIdx.y;       // v base
#pragma unroll
    for (int j = 0; j < 32; j += 8)
        g_Wt[(size_t)(y + j) * VV + x] = tile[threadIdx.x][threadIdx.y + j];
}

// ---------------------------------------------------------------------------
// Kernel 3: per-batch chunk-boundary states.
// Grid: BB blocks x VV threads (thread u owns one logit lane).
// state[b][c][u] = bias[u] + sum of Wt[v][u] over v with ft < c*CHUNK.
// Column loads batched 8-wide to keep 8 L2 loads in flight.
// ---------------------------------------------------------------------------
__global__ void boundary_states(const float* __restrict__ bias) {
    const int b = blockIdx.x;
    const int u = threadIdx.x;

    __shared__ int s_list[VV];
    __shared__ int s_cnt;

    const int myft = g_ft[b * VV + u];   // thread u doubles as scanner of code u
    float L = bias[u];

    for (int c = 0; c < NCHUNK; c++) {
        g_states[((size_t)b * NCHUNK + c) * VV + u] = L;
        if (c == NCHUNK - 1) break;      // last chunk's adds feed no boundary

        if (u == 0) s_cnt = 0;
        __syncthreads();
        if (myft >= c * CHUNK && myft < (c + 1) * CHUNK) {
            int idx = atomicAdd(&s_cnt, 1);
            s_list[idx] = u;
        }
        __syncthreads();
        const int cnt = s_cnt;

        int i = 0;
        for (; i + 8 <= cnt; i += 8) {
            float w0 = g_Wt[s_list[i + 0] * VV + u];
            float w1 = g_Wt[s_list[i + 1] * VV + u];
            float w2 = g_Wt[s_list[i + 2] * VV + u];
            float w3 = g_Wt[s_list[i + 3] * VV + u];
            float w4 = g_Wt[s_list[i + 4] * VV + u];
            float w5 = g_Wt[s_list[i + 5] * VV + u];
            float w6 = g_Wt[s_list[i + 6] * VV + u];
            float w7 = g_Wt[s_list[i + 7] * VV + u];
            L += ((w0 + w1) + (w2 + w3)) + ((w4 + w5) + (w6 + w7));
        }
        for (; i < cnt; i++) L += g_Wt[s_list[i] * VV + u];
        __syncthreads();   // protect s_cnt/s_list reuse next chunk
    }
}

// ---------------------------------------------------------------------------
// Kernel 4: emit output rows.
// Grid: (NCHUNK, BB) blocks x 128 threads; thread owns float4 lane (4 u's).
// Buckets this chunk's activations by t (time-sorted), then sweeps t with a
// depth-8 software-pipelined prefetch of Wt columns. Masked tail rows -> 0.
// ---------------------------------------------------------------------------
__global__ void emit(const int* __restrict__ lengths, float* __restrict__ out) {
    const int c   = blockIdx.x;
    const int b   = blockIdx.y;
    const int tid = threadIdx.x;           // 0..127 == CHUNK
    const int t0  = c * CHUNK;
    const int t1  = min(t0 + CHUNK, TM1);

    __shared__ int s_cnt[CHUNK];            // counts, then scatter cursors
    __shared__ int s_off[CHUNK + 1];
    __shared__ int s_list[VV];              // activation v's, time-sorted
    __shared__ int s_time[VV];              // matching activation times

    s_cnt[tid] = 0;
    __syncthreads();

    // Count activations per t (coalesced ft reads: v = k*128 + tid)
#pragma unroll
    for (int k = 0; k < 4; k++) {
        int v = k * CHUNK + tid;
        int f = g_ft[b * VV + v];
        if (f >= t0 && f < t0 + CHUNK) atomicAdd(&s_cnt[f - t0], 1);
    }
    __syncthreads();
    if (tid == 0) {
        int acc = 0;
        for (int i = 0; i < CHUNK; i++) { s_off[i] = acc; acc += s_cnt[i]; }
        s_off[CHUNK] = acc;
    }
    __syncthreads();
    s_cnt[tid] = s_off[tid];                // cursors
    __syncthreads();
#pragma unroll
    for (int k = 0; k < 4; k++) {
        int v = k * CHUNK + tid;
        int f = g_ft[b * VV + v];
        if (f >= t0 && f < t0 + CHUNK) {
            int idx = atomicAdd(&s_cnt[f - t0], 1);
            s_list[idx] = v;
            s_time[idx] = f;
        }
    }
    __syncthreads();

    // Running logits for this chunk
    float4 L = ((const float4*)(g_states + ((size_t)b * NCHUNK + c) * VV))[tid];

    const int limit  = lengths[b] - 1;      // valid t: t < limit
    const int tv_end = min(limit, t1);
    const int cnt    = s_off[CHUNK];

    float4* obase = (float4*)out + (size_t)b * TM1 * (VV / 4) + tid;

    // Depth-8 prefetch pipeline over Wt columns
    const int D = 8;
    float4 buf[D];
#pragma unroll
    for (int j = 0; j < D; j++)
        if (j < cnt) buf[j] = ((const float4*)(g_Wt + (size_t)s_list[j] * VV))[tid];

    int wt = t0;
    for (int i = 0; i < cnt; i++) {
        int ti = s_time[i];
        if (ti >= tv_end) break;            // activation past valid region
        while (wt < ti) { obase[(size_t)wt * (VV / 4)] = L; wt++; }
        float4 w = buf[i & (D - 1)];
        L.x += w.x; L.y += w.y; L.z += w.z; L.w += w.w;
        if (i + D < cnt)
            buf[i & (D - 1)] = ((const float4*)(g_Wt + (size_t)s_list[i + D] * VV))[tid];
    }
    while (wt < tv_end) { obase[(size_t)wt * (VV / 4)] = L; wt++; }

    // Masked tail: explicit zeros (d_out is poisoned)
    float4 z = make_float4(0.f, 0.f, 0.f, 0.f);
    for (int t = max(t0, tv_end); t < t1; t++)
        obase[(size_t)t * (VV / 4)] = z;
}

// ---------------------------------------------------------------------------
// Launch: inputs (metadata order): times[B,T] f32, codes[B,T,V] f32,
// lengths[B] i32, W[V,V] f32, b[V] f32. Output: [B, T-1, V] f32.
// ---------------------------------------------------------------------------
extern "C" void kernel_launch(void* const* d_in, const int* in_sizes, int n_in,
                              void* d_out, int out_size) {
    const float* codes   = (const float*)d_in[1];
    const int*   lengths = (const int*)d_in[2];
    const float* W       = (const float*)d_in[3];
    const float* bias    = (const float*)d_in[4];
    float*       out     = (float*)d_out;

    find_first<<<BB, VV>>>(codes);
    transpose_w<<<dim3(VV / 32, VV / 32), dim3(32, 8)>>>(W);
    boundary_states<<<BB, VV>>>(bias);
    emit<<<dim3(NCHUNK, BB), CHUNK>>>(lengths, out);
}